// round 15
// baseline (speedup 1.0000x reference)
#include <cuda_runtime.h>

#define BB 8
#define TTOT 100
#define NITEMS_ACC (BB * TTOT)
#define NN 100000
#define MARGIN_F 0.1f
#define THRESH_F 0.5f
#define T_TILE 10
#define NTT (TTOT / T_TILE)
#define NSPLIT 32
#define NTHREADS 256
#define NWORK (BB * NTT * NSPLIT)      // 2560 work items
#define GRID 444                       // 3/SM * 148 SMs (all resident)
#define PTS_PER_BLK ((NN + GRID - 1) / GRID)   // 226

// Device-global scratch (no allocation). All mutable state is re-initialized
// each launch (Phase A) or reset by the last block, so graph replays are clean.
__device__ float4       g_retraj[NITEMS_ACC];  // (rx,ry,rz,0)
__device__ float        g_lb[BB][3], g_ub[BB][3];     // expanded (mask) box
__device__ float        g_rlb[BB][3], g_rub[BB][3];   // raw traj AABB
__device__ float4       g_ctab[BB * NN];       // compacted (x,y,z,w)
__device__ unsigned     g_cnt[BB];             // compacted counts
__device__ int          g_acc[NITEMS_ACC];
__device__ unsigned     g_bar1, g_bar2, g_work, g_done;

__device__ __forceinline__ float fast_sqrt(float x) {
    float r;
    asm("sqrt.approx.f32 %0, %1;" : "=f"(r) : "f"(x));
    return r;
}
__device__ __forceinline__ void grid_barrier(unsigned* bar, int tid) {
    __threadfence();
    __syncthreads();
    if (tid == 0) {
        atomicAdd(bar, 1u);
        while (*((volatile unsigned*)bar) < GRID) __nanosleep(64);
    }
    __syncthreads();
    __threadfence();
}

__global__ void __launch_bounds__(NTHREADS, 3) fused_kernel(
    const float* __restrict__ outputs,
    const float* __restrict__ c2ws,
    const float* __restrict__ ss,
    const float* __restrict__ means,
    const float* __restrict__ scales,
    float* __restrict__ out)
{
    const int tid  = threadIdx.x;
    const int lane = tid & 31;
    const int wrp  = tid >> 5;
    const int gi   = blockIdx.x * NTHREADS + tid;
    const int gstr = GRID * NTHREADS;

    // ================= Phase A: init + retrajs + bounds =================
    for (int i = gi; i < NITEMS_ACC; i += gstr) g_acc[i] = 0;
    if (gi < BB) g_cnt[gi] = 0;

    if (blockIdx.x < BB) {
        const int b = blockIdx.x;
        __shared__ float4 sh_r[TTOT];
        if (tid < TTOT) {
            const float  sb = ss[b];
            const float* o  = outputs + (b * TTOT + tid) * 3;
            const float* M  = c2ws + b * 16;
            float o0 = o[0], o1 = o[1], o2 = o[2];
            float r0 = fmaf(o0, M[0] * sb, fmaf(o1, M[1] * sb, fmaf(o2, M[2]  * sb, M[3])));
            float r1 = fmaf(o0, M[4] * sb, fmaf(o1, M[5] * sb, fmaf(o2, M[6]  * sb, M[7])));
            float r2 = fmaf(o0, M[8] * sb, fmaf(o1, M[9] * sb, fmaf(o2, M[10] * sb, M[11])));
            float4 v = make_float4(r0, r1, r2, 0.0f);
            g_retraj[b * TTOT + tid] = v;
            sh_r[tid] = v;
        }
        __syncthreads();
        if (wrp < 3) {
            float mn = 1e30f, mx = -1e30f;
            for (int t = lane; t < TTOT; t += 32) {
                float4 rr = sh_r[t];
                float v = (wrp == 0) ? rr.x : ((wrp == 1) ? rr.y : rr.z);
                mn = fminf(mn, v);
                mx = fmaxf(mx, v);
            }
            #pragma unroll
            for (int o = 16; o > 0; o >>= 1) {
                mn = fminf(mn, __shfl_xor_sync(0xffffffffu, mn, o));
                mx = fmaxf(mx, __shfl_xor_sync(0xffffffffu, mx, o));
            }
            if (lane == 0) {
                float thres = THRESH_F * ss[0];
                g_rlb[b][wrp] = mn;
                g_rub[b][wrp] = mx;
                g_lb[b][wrp]  = mn - thres;
                g_ub[b][wrp]  = mx + thres;
            }
        }
    }
    grid_barrier(&g_bar1, tid);

    // ===== Phase B: per-b compaction (mask + raw-AABB distance prune) ====
    {
        __shared__ float sLB[BB][3], sUB[BB][3], sRL[BB][3], sRU[BB][3];
        __shared__ unsigned s_c[BB], s_base[BB];
        if (tid < BB * 3) {
            int b = tid / 3, e = tid - b * 3;
            sLB[b][e] = g_lb[b][e];
            sUB[b][e] = g_ub[b][e];
            sRL[b][e] = g_rlb[b][e];
            sRU[b][e] = g_rub[b][e];
        }
        const int p0 = blockIdx.x * PTS_PER_BLK;
        const int p1 = (p0 + PTS_PER_BLK > NN) ? NN : (p0 + PTS_PER_BLK);

        if (tid < BB) s_c[tid] = 0;
        __syncthreads();

        int n = p0 + tid;                    // PTS_PER_BLK <= NTHREADS: one pass
        bool valid = (n < p1);
        float x = 0.f, y = 0.f, z = 0.f, wbase = 0.f;
        unsigned lslot[BB];
        unsigned insmask = 0;
        if (valid) {
            x = means[n * 3 + 0];
            y = means[n * 3 + 1];
            z = means[n * 3 + 2];
            float s0 = scales[n * 3 + 0];
            float s1 = scales[n * 3 + 1];
            float s2 = scales[n * 3 + 2];
            wbase = fmaxf(s0, fmaxf(s1, s2)) + MARGIN_F;
            float w2 = wbase * wbase;
            #pragma unroll
            for (int b = 0; b < BB; b++) {
                bool ins = (x >= sLB[b][0]) & (x <= sUB[b][0]) &
                           (y >= sLB[b][1]) & (y <= sUB[b][1]) &
                           (z >= sLB[b][2]) & (z <= sUB[b][2]);
                // distance to raw traj AABB lower-bounds dist to every q_t
                float d0 = fmaxf(fmaxf(sRL[b][0] - x, x - sRU[b][0]), 0.0f);
                float d1 = fmaxf(fmaxf(sRL[b][1] - y, y - sRU[b][1]), 0.0f);
                float d2 = fmaxf(fmaxf(sRL[b][2] - z, z - sRU[b][2]), 0.0f);
                float dm2 = fmaf(d0, d0, fmaf(d1, d1, d2 * d2));
                if (ins & (dm2 < w2)) {
                    lslot[b] = atomicAdd(&s_c[b], 1u);
                    insmask |= (1u << b);
                }
            }
        }
        __syncthreads();
        if (tid < BB) s_base[tid] = atomicAdd(&g_cnt[tid], s_c[tid]);
        __syncthreads();
        if (valid && insmask) {
            float4 entry = make_float4(x, y, z, wbase);
            #pragma unroll
            for (int b = 0; b < BB; b++) {
                if (insmask & (1u << b))
                    g_ctab[b * NN + (s_base[b] + lslot[b])] = entry;
            }
        }
    }
    grid_barrier(&g_bar2, tid);

    // ===== Phase C: flat eval over compacted per-b lists (1 LDG/visit) ===
    __shared__ unsigned sh_item;
    __shared__ float red[T_TILE][NTHREADS / 32];
    for (;;) {
        if (tid == 0) sh_item = atomicAdd(&g_work, 1u);
        __syncthreads();
        unsigned it = sh_item;
        __syncthreads();
        if (it >= NWORK) break;

        const int b  = it / (NTT * NSPLIT);
        const int r_ = it - b * (NTT * NSPLIT);
        const int tt = r_ / NSPLIT;
        const int s  = r_ - tt * NSPLIT;
        const int tbase = tt * T_TILE;

        const int cb = (int)g_cnt[b];
        const int chunk = (cb + NSPLIT - 1) / NSPLIT;
        const int n0 = s * chunk;
        int n1 = n0 + chunk; if (n1 > cb) n1 = cb;

        float rx[T_TILE], ry[T_TILE], rz[T_TILE], acc[T_TILE];
        #pragma unroll
        for (int j = 0; j < T_TILE; j++) {
            float4 rr = g_retraj[b * TTOT + tbase + j];
            rx[j] = rr.x; ry[j] = rr.y; rz[j] = rr.z;
            acc[j] = 0.0f;
        }

        const float4* __restrict__ tab = g_ctab + (size_t)b * NN;

        #pragma unroll 4
        for (int n = n0 + tid; n < n1; n += NTHREADS) {
            float4 p = tab[n];
            #pragma unroll
            for (int j = 0; j < T_TILE; j++) {
                float dx = rx[j] - p.x;
                float dy = ry[j] - p.y;
                float dz = rz[j] - p.z;
                float d2 = fmaf(dx, dx, fmaf(dy, dy, dz * dz));
                float v  = p.w - fast_sqrt(d2);
                acc[j] = fmaxf(acc[j], v);
            }
        }

        #pragma unroll
        for (int j = 0; j < T_TILE; j++) {
            float v = acc[j];
            #pragma unroll
            for (int o = 16; o > 0; o >>= 1)
                v = fmaxf(v, __shfl_xor_sync(0xffffffffu, v, o));
            if (lane == 0) red[j][wrp] = v;
        }
        __syncthreads();
        if (tid < T_TILE) {
            float v = red[tid][0];
            #pragma unroll
            for (int w = 1; w < NTHREADS / 32; w++)
                v = fmaxf(v, red[tid][w]);
            if (v > 0.0f)
                atomicMax(&g_acc[b * TTOT + tbase + tid], __float_as_int(v));
        }
        __syncthreads();
    }

    // ============ Last finishing block: final sum + state reset ==========
    __shared__ bool isLast;
    __threadfence();
    if (tid == 0) {
        unsigned prev = atomicAdd(&g_done, 1u);
        isLast = (prev == (unsigned)(GRID - 1));
    }
    __syncthreads();
    if (isLast) {
        __shared__ float sh[NTHREADS];
        float sum = 0.0f;
        for (int i = tid; i < NITEMS_ACC; i += NTHREADS)
            sum += __int_as_float(g_acc[i]);
        sh[tid] = sum;
        __syncthreads();
        for (int o = NTHREADS / 2; o > 0; o >>= 1) {
            if (tid < o) sh[tid] += sh[tid + o];
            __syncthreads();
        }
        if (tid == 0) {
            out[0] = sh[0] / (float)NITEMS_ACC;
            g_work = 0; g_done = 0;
            g_bar1 = 0; g_bar2 = 0;
        }
    }
}

extern "C" void kernel_launch(void* const* d_in, const int* in_sizes, int n_in,
                              void* d_out, int out_size) {
    const float* outputs = (const float*)d_in[0];  // (8,100,3)
    const float* c2ws    = (const float*)d_in[1];  // (8,4,4)
    const float* ss      = (const float*)d_in[2];  // (8,)
    const float* means   = (const float*)d_in[3];  // (100000,3)
    const float* scales  = (const float*)d_in[4];  // (100000,3)
    float* out = (float*)d_out;

    fused_kernel<<<GRID, NTHREADS>>>(outputs, c2ws, ss, means, scales, out);
}